// round 13
// baseline (speedup 1.0000x reference)
#include <cuda_runtime.h>
#include <cuda_fp16.h>

#define CDIM 64
#define KK   25
#define KO   (CDIM * KK)   // 1600
#define MAXN 50000
#define MAXE 800000

typedef unsigned long long ull;
typedef unsigned int uint32;

// ---------------- scratch (static device globals; no allocation) ------------
__device__ __half g_xW[(size_t)MAXN * KO];   // 160 MB (fp16), reused by both layers
__device__ float  g_x1[(size_t)MAXN * CDIM];
__device__ float  g_x2[(size_t)MAXN * CDIM];
__device__ float  g_facc[(size_t)MAXN * CDIM];   // final-gemm partial acc
__device__ __half g_x16[(size_t)MAXN * CDIM];
__device__ __half g_W16a[KK * CDIM * CDIM];
__device__ __half g_W16b[KK * CDIM * CDIM];
__device__ int    g_counts[MAXN];
__device__ int    g_rowptr[MAXN + 1];
__device__ int    g_cursor[MAXN];
__device__ int2   g_sw[MAXE];
__device__ float4 g_basis[MAXE];

// ---------------- streams + events + L2 policy (once, at process init) -------
struct SideStream {
    cudaStream_t s1, s2;
    cudaEvent_t  ev_fork, ev_csr, ev_agg1, ev_pf, ev_done;
    SideStream() {
        cudaStreamCreateWithFlags(&s1, cudaStreamNonBlocking);
        cudaStreamCreateWithFlags(&s2, cudaStreamNonBlocking);
        cudaEventCreateWithFlags(&ev_fork, cudaEventDisableTiming);
        cudaEventCreateWithFlags(&ev_csr,  cudaEventDisableTiming);
        cudaEventCreateWithFlags(&ev_agg1, cudaEventDisableTiming);
        cudaEventCreateWithFlags(&ev_pf,   cudaEventDisableTiming);
        cudaEventCreateWithFlags(&ev_done, cudaEventDisableTiming);

        // Persisting-L2 window over the low part of g_xW. Best-effort: if any
        // call fails the policy silently no-ops and behavior is unchanged.
        cudaDeviceProp prop{};
        cudaGetDeviceProperties(&prop, 0);
        size_t persist = (size_t)prop.persistingL2CacheMaxSize;
        if (persist > 0) {
            cudaDeviceSetLimit(cudaLimitPersistingL2CacheSize, persist);
            void* xwp = nullptr;
            cudaGetSymbolAddress(&xwp, g_xW);
            size_t win = (size_t)prop.accessPolicyMaxWindowSize;
            if (win > persist) win = persist;
            size_t total = (size_t)MAXN * KO * sizeof(__half);
            if (win > total) win = total;
            if (xwp && win > 0) {
                cudaStreamAttrValue v{};
                v.accessPolicyWindow.base_ptr  = xwp;
                v.accessPolicyWindow.num_bytes = win;
                v.accessPolicyWindow.hitRatio  = 1.0f;
                v.accessPolicyWindow.hitProp   = cudaAccessPropertyPersisting;
                v.accessPolicyWindow.missProp  = cudaAccessPropertyStreaming;
                cudaStreamSetAttribute(s1, cudaStreamAttributeAccessPolicyWindow, &v);
                cudaStreamSetAttribute(s2, cudaStreamAttributeAccessPolicyWindow, &v);
            }
        }
    }
};
static SideStream g_ss;

// ---------------- packed f32x2 helpers ---------------------------------------
__device__ __forceinline__ float2 ffma2(float2 a, ull b, float2 c) {
    ull au = *reinterpret_cast<ull*>(&a);
    ull cu = *reinterpret_cast<ull*>(&c);
    ull du;
    asm("fma.rn.f32x2 %0, %1, %2, %3;" : "=l"(du) : "l"(au), "l"(b), "l"(cu));
    return *reinterpret_cast<float2*>(&du);
}
__device__ __forceinline__ ull dup2(float b) {
    ull r;
    asm("mov.b64 %0, {%1, %1};" : "=l"(r) : "f"(b));
    return r;
}

// ---------------- mma / ldmatrix helpers -------------------------------------
__device__ __forceinline__ void mma16816(float c[4], const uint32 a[4],
                                         uint32 b0, uint32 b1) {
    asm volatile("mma.sync.aligned.m16n8k16.row.col.f32.f16.f16.f32 "
                 "{%0,%1,%2,%3}, {%4,%5,%6,%7}, {%8,%9}, {%0,%1,%2,%3};"
                 : "+f"(c[0]), "+f"(c[1]), "+f"(c[2]), "+f"(c[3])
                 : "r"(a[0]), "r"(a[1]), "r"(a[2]), "r"(a[3]), "r"(b0), "r"(b1));
}
__device__ __forceinline__ void ldsm_x4(uint32 r[4], uint32 addr) {
    asm volatile("ldmatrix.sync.aligned.m8n8.x4.shared.b16 {%0,%1,%2,%3}, [%4];"
                 : "=r"(r[0]), "=r"(r[1]), "=r"(r[2]), "=r"(r[3]) : "r"(addr));
}
__device__ __forceinline__ void ldsm_x2t(uint32& r0, uint32& r1, uint32 addr) {
    asm volatile("ldmatrix.sync.aligned.m8n8.x2.trans.shared.b16 {%0,%1}, [%2];"
                 : "=r"(r0), "=r"(r1) : "r"(addr));
}

__device__ __forceinline__ __half2 ldcg_h2(const __half2* p) {
    uint32 v;
    asm volatile("ld.global.cg.b32 %0, [%1];" : "=r"(v) : "l"(p));
    return *reinterpret_cast<__half2*>(&v);
}

// ---------------- fp32 -> fp16 conversion ------------------------------------
__global__ void f2h_kernel(const float* __restrict__ in, __half* __restrict__ out,
                           int n4) {
    int i = blockIdx.x * blockDim.x + threadIdx.x;
    if (i < n4) {
        float4 v = ((const float4*)in)[i];
        union { uint2 u; __half2 h[2]; } pk;
        pk.h[0] = __floats2half2_rn(v.x, v.y);
        pk.h[1] = __floats2half2_rn(v.z, v.w);
        ((uint2*)out)[i] = pk.u;
    }
}

// ---------------- CSR build -------------------------------------------------
__global__ void zero_counts_kernel(int N) {
    int i = blockIdx.x * blockDim.x + threadIdx.x;
    if (i < N) g_counts[i] = 0;
}

__global__ void count_kernel(const int* __restrict__ ei, int E) {
    int e = blockIdx.x * blockDim.x + threadIdx.x;
    if (e < E) atomicAdd(&g_counts[ei[E + e]], 1);
}

__global__ void scan_kernel(int N) {
    __shared__ int warp_off[32];
    __shared__ int s_carry;
    int tid  = threadIdx.x;
    int lane = tid & 31;
    int wid  = tid >> 5;
    if (tid == 0) s_carry = 0;
    __syncthreads();
    for (int base = 0; base < N; base += 1024) {
        int i = base + tid;
        int v = (i < N) ? g_counts[i] : 0;
        int incl = v;
        #pragma unroll
        for (int off = 1; off < 32; off <<= 1) {
            int t = __shfl_up_sync(0xffffffffu, incl, off);
            if (lane >= off) incl += t;
        }
        if (lane == 31) warp_off[wid] = incl;
        __syncthreads();
        if (wid == 0) {
            int s = warp_off[lane];
            int si = s;
            #pragma unroll
            for (int off = 1; off < 32; off <<= 1) {
                int t = __shfl_up_sync(0xffffffffu, si, off);
                if (lane >= off) si += t;
            }
            warp_off[lane] = si - s;
        }
        __syncthreads();
        int excl = incl - v + warp_off[wid] + s_carry;
        if (i < N) { g_rowptr[i] = excl; g_cursor[i] = excl; }
        __syncthreads();
        if (tid == 1023) s_carry = excl + v;
        __syncthreads();
    }
    if (tid == 0) g_rowptr[N] = s_carry;
}

__global__ void scatter_kernel(const int* __restrict__ ei,
                               const float* __restrict__ attr, int E) {
    int e = blockIdx.x * blockDim.x + threadIdx.x;
    if (e >= E) return;
    int src = ei[e];
    int dst = ei[E + e];

    float p0 = attr[2 * e + 0];
    float p1 = attr[2 * e + 1];
    float v0 = p0 * 4.0f, v1 = p1 * 4.0f;
    float l0 = floorf(v0), l1 = floorf(v1);
    float f0 = v0 - l0,    f1 = v1 - l1;
    int i0 = (int)l0, i1 = (int)l1;
    int i00 = min(max(i0, 0), 4);
    int i01 = min(max(i0 + 1, 0), 4);
    int i10 = min(max(i1, 0), 4);
    int i11 = min(max(i1 + 1, 0), 4);

    float4 b;
    b.x = (1.0f - f0) * (1.0f - f1);
    b.y = (1.0f - f0) * f1;
    b.z = f0 * (1.0f - f1);
    b.w = f0 * f1;
    int wp = (i00 + 5 * i10)
           | ((i00 + 5 * i11) << 8)
           | ((i01 + 5 * i10) << 16)
           | ((i01 + 5 * i11) << 24);

    int pos = atomicAdd(&g_cursor[dst], 1);
    g_sw[pos]    = make_int2(src, wp);
    g_basis[pos] = b;
}

// ---------------- HMMA GEMM, k-batched, double-buffered W, smem epilogue -----
#define KBATCH 5
__global__ void __launch_bounds__(128, 4)
gemm_xw_hmma(const __half* __restrict__ X16,
             const __half* __restrict__ W16, int N) {
    __shared__ __half xs[128][72];
    __shared__ __half ws[2][64][72];
    int row0 = blockIdx.x * 128;
    int k0   = blockIdx.y * KBATCH;
    int tid  = threadIdx.x;

    #pragma unroll
    for (int t = tid; t < 1024; t += 128) {
        int r = t >> 3, c8 = (t & 7) * 8;
        int gr = row0 + r;
        uint4 v = make_uint4(0, 0, 0, 0);
        if (gr < N) v = *(const uint4*)&X16[(size_t)gr * CDIM + c8];
        *(uint4*)&xs[r][c8] = v;
    }
    #pragma unroll
    for (int t = tid; t < 512; t += 128) {
        int r = t >> 3, c8 = (t & 7) * 8;
        *(uint4*)&ws[0][r][c8] = *(const uint4*)&W16[k0 * 4096 + r * 64 + c8];
    }
    __syncthreads();

    int warp = tid >> 5, lane = tid & 31;
    int m_base = warp * 32;

    uint32 a[2][4][4];
    #pragma unroll
    for (int mt = 0; mt < 2; ++mt)
        #pragma unroll
        for (int kt = 0; kt < 4; ++kt) {
            uint32 addr = (uint32)__cvta_generic_to_shared(
                &xs[m_base + mt * 16 + (lane & 15)][kt * 16 + (lane >> 4) * 8]);
            ldsm_x4(a[mt][kt], addr);
        }

    for (int kk = 0; kk < KBATCH; ++kk) {
        int k   = k0 + kk;
        int cur = kk & 1;

        if (kk + 1 < KBATCH) {
            #pragma unroll
            for (int t = tid; t < 512; t += 128) {
                int r = t >> 3, c8 = (t & 7) * 8;
                *(uint4*)&ws[cur ^ 1][r][c8] =
                    *(const uint4*)&W16[(k + 1) * 4096 + r * 64 + c8];
            }
        }

        float c[2][8][4];
        #pragma unroll
        for (int mt = 0; mt < 2; ++mt)
            #pragma unroll
            for (int nt = 0; nt < 8; ++nt)
                #pragma unroll
                for (int j = 0; j < 4; ++j) c[mt][nt][j] = 0.f;

        #pragma unroll
        for (int kt = 0; kt < 4; ++kt) {
            #pragma unroll
            for (int nt = 0; nt < 8; ++nt) {
                uint32 baddr = (uint32)__cvta_generic_to_shared(
                    &ws[cur][kt * 16 + (lane & 15)][nt * 8]);
                uint32 b0, b1;
                ldsm_x2t(b0, b1, baddr);
                mma16816(c[0][nt], a[0][kt], b0, b1);
                mma16816(c[1][nt], a[1][kt], b0, b1);
            }
        }

        int fr = lane >> 2;
        int fc = 2 * (lane & 3);
        #pragma unroll
        for (int mt = 0; mt < 2; ++mt) {
            #pragma unroll
            for (int nt = 0; nt < 8; ++nt) {
                *(__half2*)&xs[m_base + mt * 16 + fr][nt * 8 + fc] =
                    __floats2half2_rn(c[mt][nt][0], c[mt][nt][1]);
                *(__half2*)&xs[m_base + mt * 16 + 8 + fr][nt * 8 + fc] =
                    __floats2half2_rn(c[mt][nt][2], c[mt][nt][3]);
            }
        }
        __syncwarp();
        #pragma unroll
        for (int it = 0; it < 8; ++it) {
            int r  = m_base + it * 4 + (lane >> 3);
            int gr = row0 + r;
            if (gr < N) {
                uint4 v = *(uint4*)&xs[r][(lane & 7) * 8];
                *(uint4*)&g_xW[(size_t)gr * KO + k * 64 + (lane & 7) * 8] = v;
            }
        }
        __syncthreads();
    }
}

// ---------------- per-node aggregation (round-8 best config) -----------------
__device__ __forceinline__ float2 edge_msg(int e, int lane) {
    int2   sw = g_sw[e];
    float4 b  = g_basis[e];
    const __half2* p = (const __half2*)(g_xW + (size_t)sw.x * KO) + lane;
    unsigned w = (unsigned)sw.y;
    __half2 a0 = ldcg_h2(p + ((w      ) & 255) * 32);
    __half2 a1 = ldcg_h2(p + ((w >>  8) & 255) * 32);
    __half2 a2 = ldcg_h2(p + ((w >> 16) & 255) * 32);
    __half2 a3 = ldcg_h2(p + ((w >> 24) & 255) * 32);
    float2 f, v;
    f = __half22float2(a0); v.x = b.x * f.x;           v.y = b.x * f.y;
    f = __half22float2(a1); v.x = fmaf(b.y, f.x, v.x); v.y = fmaf(b.y, f.y, v.y);
    f = __half22float2(a2); v.x = fmaf(b.z, f.x, v.x); v.y = fmaf(b.z, f.y, v.y);
    f = __half22float2(a3); v.x = fmaf(b.w, f.x, v.x); v.y = fmaf(b.w, f.y, v.y);
    return v;
}

__global__ void __launch_bounds__(256, 3)
agg_kernel(const float* __restrict__ xin,
           const float* __restrict__ root,
           const float* __restrict__ bias,
           float* __restrict__ xout,
           __half* __restrict__ xout16, int N) {
    __shared__ float sx[8][64];
    int wib  = threadIdx.x >> 5;
    int lane = threadIdx.x & 31;
    int n    = blockIdx.x * 8 + wib;

    for (int t = threadIdx.x; t < 8 * 64; t += 256) {
        int r = t >> 6, c = t & 63;
        int gn = blockIdx.x * 8 + r;
        sx[r][c] = (gn < N) ? xin[(size_t)gn * CDIM + c] : 0.f;
    }
    __syncthreads();
    if (n >= N) return;

    int c0 = lane * 2;
    float2 r2 = make_float2(bias[c0], bias[c0 + 1]);
    #pragma unroll
    for (int i = 0; i < CDIM; ++i) {
        float  xi = sx[wib][i];
        float2 rv = *(const float2*)&root[i * CDIM + c0];
        r2.x = fmaf(xi, rv.x, r2.x);
        r2.y = fmaf(xi, rv.y, r2.y);
    }

    int beg = g_rowptr[n];
    int end = g_rowptr[n + 1];
    const float NEG = __int_as_float(0xff800000);
    float2 m0 = make_float2(NEG, NEG);
    float2 m1 = make_float2(NEG, NEG);
    float2 m2 = make_float2(NEG, NEG);
    float2 m3 = make_float2(NEG, NEG);
    int e = beg;
    for (; e + 3 < end; e += 4) {
        int2   sw[4];
        float4 bb[4];
        #pragma unroll
        for (int j = 0; j < 4; ++j) { sw[j] = g_sw[e + j]; bb[j] = g_basis[e + j]; }
        __half2 h[4][4];
        #pragma unroll
        for (int j = 0; j < 4; ++j) {
            const __half2* p = (const __half2*)(g_xW + (size_t)sw[j].x * KO) + lane;
            unsigned w = (unsigned)sw[j].y;
            h[j][0] = ldcg_h2(p + ((w      ) & 255) * 32);
            h[j][1] = ldcg_h2(p + ((w >>  8) & 255) * 32);
            h[j][2] = ldcg_h2(p + ((w >> 16) & 255) * 32);
            h[j][3] = ldcg_h2(p + ((w >> 24) & 255) * 32);
        }
        #pragma unroll
        for (int j = 0; j < 4; ++j) {
            float4 b = bb[j];
            float2 f, v;
            f = __half22float2(h[j][0]); v.x = b.x * f.x;           v.y = b.x * f.y;
            f = __half22float2(h[j][1]); v.x = fmaf(b.y, f.x, v.x); v.y = fmaf(b.y, f.y, v.y);
            f = __half22float2(h[j][2]); v.x = fmaf(b.z, f.x, v.x); v.y = fmaf(b.z, f.y, v.y);
            f = __half22float2(h[j][3]); v.x = fmaf(b.w, f.x, v.x); v.y = fmaf(b.w, f.y, v.y);
            if (j == 0) { m0.x = fmaxf(m0.x, v.x); m0.y = fmaxf(m0.y, v.y); }
            if (j == 1) { m1.x = fmaxf(m1.x, v.x); m1.y = fmaxf(m1.y, v.y); }
            if (j == 2) { m2.x = fmaxf(m2.x, v.x); m2.y = fmaxf(m2.y, v.y); }
            if (j == 3) { m3.x = fmaxf(m3.x, v.x); m3.y = fmaxf(m3.y, v.y); }
        }
    }
    for (; e < end; ++e) {
        float2 v = edge_msg(e, lane);
        m0.x = fmaxf(m0.x, v.x); m0.y = fmaxf(m0.y, v.y);
    }
    float2 m = make_float2(fmaxf(fmaxf(m0.x, m1.x), fmaxf(m2.x, m3.x)),
                           fmaxf(fmaxf(m0.y, m1.y), fmaxf(m2.y, m3.y)));
    float2 agg = (end > beg) ? m : make_float2(0.f, 0.f);
    float2 o = make_float2(fmaxf(agg.x + r2.x, 0.f), fmaxf(agg.y + r2.y, 0.f));
    *(float2*)&xout[(size_t)n * CDIM + c0] = o;
    *(__half2*)&xout16[(size_t)n * CDIM + c0] = __floats2half2_rn(o.x, o.y);
}

// ---------------- final gemm, split into partial (x, x1) and finish (x2) -----
__global__ void partial_final_kernel(const float* __restrict__ x,
                                     const float* __restrict__ fw, int N) {
    __shared__ float2 As2[64][64];
    __shared__ float  Bs[64][64];
    int row0 = blockIdx.x * 128;
    int tid  = threadIdx.x;
    int tx = tid & 7, ty = tid >> 3;

    float2 acc[4][8];
    #pragma unroll
    for (int rp = 0; rp < 4; ++rp)
        #pragma unroll
        for (int c = 0; c < 8; ++c) acc[rp][c] = make_float2(0.f, 0.f);

    for (int ch = 0; ch < 2; ++ch) {
        const float* S = (ch == 0) ? x : g_x1;
        __syncthreads();
        #pragma unroll
        for (int t = tid; t < 128 * 16; t += 128) {
            int r = t >> 4, c4 = (t & 15) * 4;
            int gr = row0 + r;
            float4 v = make_float4(0.f, 0.f, 0.f, 0.f);
            if (gr < N) v = *(const float4*)&S[(size_t)gr * CDIM + c4];
            float* dstp0 = (float*)&As2[r >> 1][c4 + 0];
            int l = r & 1;
            dstp0[l]     = v.x;
            dstp0[2 + l] = v.y;
            dstp0[4 + l] = v.z;
            dstp0[6 + l] = v.w;
        }
        #pragma unroll
        for (int t = tid; t < 64 * 16; t += 128) {
            int r = t >> 4, c4 = (t & 15) * 4;
            *(float4*)&Bs[r][c4] = *(const float4*)&fw[ch * 4096 + r * 64 + c4];
        }
        __syncthreads();

        #pragma unroll 16
        for (int i = 0; i < 64; ++i) {
            float2 ap[4];
            #pragma unroll
            for (int rp = 0; rp < 4; ++rp) ap[rp] = As2[ty * 4 + rp][i];
            float4 b0 = *(const float4*)&Bs[i][tx * 8];
            float4 b1 = *(const float4*)&Bs[i][tx * 8 + 4];
            ull bb[8];
            bb[0] = dup2(b0.x); bb[1] = dup2(b0.y); bb[2] = dup2(b0.z); bb[3] = dup2(b0.w);
            bb[4] = dup2(b1.x); bb[5] = dup2(b1.y); bb[6] = dup2(b1.z); bb[7] = dup2(b1.w);
            #pragma unroll
            for (int rp = 0; rp < 4; ++rp)
                #pragma unroll
                for (int c = 0; c < 8; ++c)
                    acc[rp][c] = ffma2(ap[rp], bb[c], acc[rp][c]);
        }
    }

    #pragma unroll
    for (int rp = 0; rp < 4; ++rp) {
        int r0 = row0 + ty * 8 + rp * 2;
        if (r0 < N) {
            float4 v0 = make_float4(acc[rp][0].x, acc[rp][1].x, acc[rp][2].x, acc[rp][3].x);
            float4 v1 = make_float4(acc[rp][4].x, acc[rp][5].x, acc[rp][6].x, acc[rp][7].x);
            *(float4*)&g_facc[(size_t)r0 * CDIM + tx * 8]     = v0;
            *(float4*)&g_facc[(size_t)r0 * CDIM + tx * 8 + 4] = v1;
        }
        if (r0 + 1 < N) {
            float4 v0 = make_float4(acc[rp][0].y, acc[rp][1].y, acc[rp][2].y, acc[rp][3].y);
            float4 v1 = make_float4(acc[rp][4].y, acc[rp][5].y, acc[rp][6].y, acc[rp][7].y);
            *(float4*)&g_facc[(size_t)(r0 + 1) * CDIM + tx * 8]     = v0;
            *(float4*)&g_facc[(size_t)(r0 + 1) * CDIM + tx * 8 + 4] = v1;
        }
    }
}

__global__ void finish_final_kernel(const float* __restrict__ fw,
                                    const float* __restrict__ fb,
                                    float* __restrict__ out, int N) {
    __shared__ float2 As2[64][64];
    __shared__ float  Bs[64][64];
    int row0 = blockIdx.x * 128;
    int tid  = threadIdx.x;
    int tx = tid & 7, ty = tid >> 3;

    float2 acc[4][8];
    #pragma unroll
    for (int rp = 0; rp < 4; ++rp)
        #pragma unroll
        for (int c = 0; c < 8; ++c) acc[rp][c] = make_float2(0.f, 0.f);

    #pragma unroll
    for (int t = tid; t < 128 * 16; t += 128) {
        int r = t >> 4, c4 = (t & 15) * 4;
        int gr = row0 + r;
        float4 v = make_float4(0.f, 0.f, 0.f, 0.f);
        if (gr < N) v = *(const float4*)&g_x2[(size_t)gr * CDIM + c4];
        float* dstp0 = (float*)&As2[r >> 1][c4 + 0];
        int l = r & 1;
        dstp0[l]     = v.x;
        dstp0[2 + l] = v.y;
        dstp0[4 + l] = v.z;
        dstp0[6 + l] = v.w;
    }
    #pragma unroll
    for (int t = tid; t < 64 * 16; t += 128) {
        int r = t >> 4, c4 = (t & 15) * 4;
        *(float4*)&Bs[r][c4] = *(const float4*)&fw[2 * 4096 + r * 64 + c4];
    }
    __syncthreads();

    #pragma unroll 16
    for (int i = 0; i < 64; ++i) {
        float2 ap[4];
        #pragma unroll
        for (int rp = 0; rp < 4; ++rp) ap[rp] = As2[ty * 4 + rp][i];
        float4 b0 = *(const float4*)&Bs[i][tx * 8];
        float4 b1 = *(const float4*)&Bs[i][tx * 8 + 4];
        ull bb[8];
        bb[0] = dup2(b0.x); bb[1] = dup2(b0.y); bb[2] = dup2(b0.z); bb[3] = dup2(b0.w);
        bb[4] = dup2(b1.x); bb[5] = dup2(b1.y); bb[6] = dup2(b1.z); bb[7] = dup2(b1.w);
        #pragma unroll
        for (int rp = 0; rp < 4; ++rp)
            #pragma unroll
            for (int c = 0; c < 8; ++c)
                acc[rp][c] = ffma2(ap[rp], bb[c], acc[rp][c]);
    }

    float4 fb0 = *(const float4*)&fb[tx * 8];
    float4 fb1 = *(const float4*)&fb[tx * 8 + 4];
    #pragma unroll
    for (int rp = 0; rp < 4; ++rp) {
        int r0 = row0 + ty * 8 + rp * 2;
        if (r0 < N) {
            float4 p0 = *(const float4*)&g_facc[(size_t)r0 * CDIM + tx * 8];
            float4 p1 = *(const float4*)&g_facc[(size_t)r0 * CDIM + tx * 8 + 4];
            float4 v0 = make_float4(acc[rp][0].x + p0.x + fb0.x, acc[rp][1].x + p0.y + fb0.y,
                                    acc[rp][2].x + p0.z + fb0.z, acc[rp][3].x + p0.w + fb0.w);
            float4 v1 = make_float4(acc[rp][4].x + p1.x + fb1.x, acc[rp][5].x + p1.y + fb1.y,
                                    acc[rp][6].x + p1.z + fb1.z, acc[rp][7].x + p1.w + fb1.w);
            *(float4*)&out[(size_t)r0 * CDIM + tx * 8]     = v0;
            *(float4*)&out[(size_t)r0 * CDIM + tx * 8 + 4] = v1;
        }
        if (r0 + 1 < N) {
            float4 p0 = *(const float4*)&g_facc[(size_t)(r0 + 1) * CDIM + tx * 8];
            float4 p1 = *(const float4*)&g_facc[(size_t)(r0 + 1) * CDIM + tx * 8 + 4];
            float4 v0 = make_float4(acc[rp][0].y + p0.x + fb0.x, acc[rp][1].y + p0.y + fb0.y,
                                    acc[rp][2].y + p0.z + fb0.z, acc[rp][3].y + p0.w + fb0.w);
            float4 v1 = make_float4(acc[rp][4].y + p1.x + fb1.x, acc[rp][5].y + p1.y + fb1.y,
                                    acc[rp][6].y + p1.z + fb1.z, acc[rp][7].y + p1.w + fb1.w);
            *(float4*)&out[(size_t)(r0 + 1) * CDIM + tx * 8]     = v0;
            *(float4*)&out[(size_t)(r0 + 1) * CDIM + tx * 8 + 4] = v1;
        }
    }
}

// ---------------- launch -----------------------------------------------------
extern "C" void kernel_launch(void* const* d_in, const int* in_sizes, int n_in,
                              void* d_out, int out_size) {
    const float* x     = (const float*)d_in[0];
    const int*   ei    = (const int*)  d_in[1];
    const float* attr  = (const float*)d_in[2];
    const float* W1    = (const float*)d_in[3];
    const float* root1 = (const float*)d_in[4];
    const float* b1    = (const float*)d_in[5];
    const float* W2    = (const float*)d_in[6];
    const float* root2 = (const float*)d_in[7];
    const float* b2    = (const float*)d_in[8];
    const float* fw    = (const float*)d_in[9];
    const float* fb    = (const float*)d_in[10];
    float* out = (float*)d_out;

    int N = in_sizes[0] / CDIM;
    int E = in_sizes[1] / 2;
    if (N > MAXN) N = MAXN;
    if (E > MAXE) E = MAXE;

    float *px1 = nullptr, *px2 = nullptr;
    __half *px16 = nullptr, *pw16a = nullptr, *pw16b = nullptr;
    cudaGetSymbolAddress((void**)&px1, g_x1);
    cudaGetSymbolAddress((void**)&px2, g_x2);
    cudaGetSymbolAddress((void**)&px16, g_x16);
    cudaGetSymbolAddress((void**)&pw16a, g_W16a);
    cudaGetSymbolAddress((void**)&pw16b, g_W16b);

    int eb = (E + 255) / 256;
    int nb = (N + 255) / 256;
    dim3 ggrid((N + 127) / 128, KK / KBATCH);
    int ab = (N + 7) / 8;
    int fgrid = (N + 127) / 128;

    int xq = N * CDIM / 4;
    int wq = KK * CDIM * CDIM / 4;

    cudaStream_t s1 = g_ss.s1;
    cudaStream_t s2 = g_ss.s2;

    // fork from harness stream
    cudaEventRecord(g_ss.ev_fork, 0);
    cudaStreamWaitEvent(s1, g_ss.ev_fork, 0);
    cudaStreamWaitEvent(s2, g_ss.ev_fork, 0);

    // side stream: CSR build + W2 conversion
    zero_counts_kernel<<<nb, 256, 0, s2>>>(N);
    count_kernel<<<eb, 256, 0, s2>>>(ei, E);
    scan_kernel<<<1, 1024, 0, s2>>>(N);
    scatter_kernel<<<eb, 256, 0, s2>>>(ei, attr, E);
    f2h_kernel<<<(wq + 255) / 256, 256, 0, s2>>>(W2, pw16b, wq);
    cudaEventRecord(g_ss.ev_csr, s2);

    // main chain on s1
    f2h_kernel<<<(xq + 255) / 256, 256, 0, s1>>>(x, px16, xq);
    f2h_kernel<<<(wq + 255) / 256, 256, 0, s1>>>(W1, pw16a, wq);
    gemm_xw_hmma<<<ggrid, 128, 0, s1>>>(px16, pw16a, N);
    cudaStreamWaitEvent(s1, g_ss.ev_csr, 0);
    agg_kernel<<<ab, 256, 0, s1>>>(x, root1, b1, px1, px16, N);
    cudaEventRecord(g_ss.ev_agg1, s1);

    // side stream: partial final (x, x1) overlaps layer 2
    cudaStreamWaitEvent(s2, g_ss.ev_agg1, 0);
    partial_final_kernel<<<fgrid, 128, 0, s2>>>(x, fw, N);
    cudaEventRecord(g_ss.ev_pf, s2);

    // layer 2 on s1
    gemm_xw_hmma<<<ggrid, 128, 0, s1>>>(px16, pw16b, N);
    agg_kernel<<<ab, 256, 0, s1>>>(px1, root2, b2, px2, px16, N);

    // finish final on s1
    cudaStreamWaitEvent(s1, g_ss.ev_pf, 0);
    finish_final_kernel<<<fgrid, 128, 0, s1>>>(fw, fb, out, N);

    // join back to harness stream
    cudaEventRecord(g_ss.ev_done, s1);
    cudaStreamWaitEvent(0, g_ss.ev_done, 0);
}

// round 14
// speedup vs baseline: 1.1256x; 1.1256x over previous
#include <cuda_runtime.h>
#include <cuda_fp16.h>

#define CDIM 64
#define KK   25
#define KO   (CDIM * KK)   // 1600
#define MAXN 50000
#define MAXE 800000

typedef unsigned long long ull;
typedef unsigned int uint32;

// ---------------- scratch (static device globals; no allocation) ------------
__device__ __half g_xW[(size_t)MAXN * KO];   // 160 MB (fp16), reused by both layers
__device__ float  g_x1[(size_t)MAXN * CDIM];
__device__ float  g_x2[(size_t)MAXN * CDIM];
__device__ float  g_facc[(size_t)MAXN * CDIM];   // final-gemm partial acc
__device__ __half g_x16[(size_t)MAXN * CDIM];
__device__ __half g_W16a[KK * CDIM * CDIM];
__device__ __half g_W16b[KK * CDIM * CDIM];
__device__ int    g_counts[MAXN];
__device__ int    g_rowptr[MAXN + 1];
__device__ int    g_cursor[MAXN];
__device__ float4 g_meta[2 * MAXE];   // per edge: {src,wi,bx,by},{bz,bw,-,-}
__device__ int    g_work[2];          // work-stealing counters (per layer)

// ---------------- streams + events (once, at process init) -------------------
struct SideStream {
    cudaStream_t s1, s2;
    cudaEvent_t  ev_fork, ev_csr, ev_agg1, ev_pf, ev_done;
    SideStream() {
        cudaStreamCreateWithFlags(&s1, cudaStreamNonBlocking);
        cudaStreamCreateWithFlags(&s2, cudaStreamNonBlocking);
        cudaEventCreateWithFlags(&ev_fork, cudaEventDisableTiming);
        cudaEventCreateWithFlags(&ev_csr,  cudaEventDisableTiming);
        cudaEventCreateWithFlags(&ev_agg1, cudaEventDisableTiming);
        cudaEventCreateWithFlags(&ev_pf,   cudaEventDisableTiming);
        cudaEventCreateWithFlags(&ev_done, cudaEventDisableTiming);
    }
};
static SideStream g_ss;

// ---------------- packed f32x2 helpers ---------------------------------------
__device__ __forceinline__ float2 ffma2(float2 a, ull b, float2 c) {
    ull au = *reinterpret_cast<ull*>(&a);
    ull cu = *reinterpret_cast<ull*>(&c);
    ull du;
    asm("fma.rn.f32x2 %0, %1, %2, %3;" : "=l"(du) : "l"(au), "l"(b), "l"(cu));
    return *reinterpret_cast<float2*>(&du);
}
__device__ __forceinline__ ull dup2(float b) {
    ull r;
    asm("mov.b64 %0, {%1, %1};" : "=l"(r) : "f"(b));
    return r;
}

// ---------------- mma / ldmatrix helpers -------------------------------------
__device__ __forceinline__ void mma16816(float c[4], const uint32 a[4],
                                         uint32 b0, uint32 b1) {
    asm volatile("mma.sync.aligned.m16n8k16.row.col.f32.f16.f16.f32 "
                 "{%0,%1,%2,%3}, {%4,%5,%6,%7}, {%8,%9}, {%0,%1,%2,%3};"
                 : "+f"(c[0]), "+f"(c[1]), "+f"(c[2]), "+f"(c[3])
                 : "r"(a[0]), "r"(a[1]), "r"(a[2]), "r"(a[3]), "r"(b0), "r"(b1));
}
__device__ __forceinline__ void ldsm_x4(uint32 r[4], uint32 addr) {
    asm volatile("ldmatrix.sync.aligned.m8n8.x4.shared.b16 {%0,%1,%2,%3}, [%4];"
                 : "=r"(r[0]), "=r"(r[1]), "=r"(r[2]), "=r"(r[3]) : "r"(addr));
}
__device__ __forceinline__ void ldsm_x2t(uint32& r0, uint32& r1, uint32 addr) {
    asm volatile("ldmatrix.sync.aligned.m8n8.x2.trans.shared.b16 {%0,%1}, [%2];"
                 : "=r"(r0), "=r"(r1) : "r"(addr));
}

__device__ __forceinline__ __half2 ldcg_h2(const __half2* p) {
    uint32 v;
    asm volatile("ld.global.cg.b32 %0, [%1];" : "=r"(v) : "l"(p));
    return *reinterpret_cast<__half2*>(&v);
}

// ---------------- fp32 -> fp16 conversion ------------------------------------
__global__ void f2h_kernel(const float* __restrict__ in, __half* __restrict__ out,
                           int n4) {
    int i = blockIdx.x * blockDim.x + threadIdx.x;
    if (i < n4) {
        float4 v = ((const float4*)in)[i];
        union { uint2 u; __half2 h[2]; } pk;
        pk.h[0] = __floats2half2_rn(v.x, v.y);
        pk.h[1] = __floats2half2_rn(v.z, v.w);
        ((uint2*)out)[i] = pk.u;
    }
}

// ---------------- CSR build -------------------------------------------------
__global__ void zero_counts_kernel(int N) {
    int i = blockIdx.x * blockDim.x + threadIdx.x;
    if (i < N) g_counts[i] = 0;
    if (i < 2) g_work[i] = 0;          // reset agg work-stealing counters
}

__global__ void count_kernel(const int* __restrict__ ei, int E) {
    int e = blockIdx.x * blockDim.x + threadIdx.x;
    if (e < E) atomicAdd(&g_counts[ei[E + e]], 1);
}

__global__ void scan_kernel(int N) {
    __shared__ int warp_off[32];
    __shared__ int s_carry;
    int tid  = threadIdx.x;
    int lane = tid & 31;
    int wid  = tid >> 5;
    if (tid == 0) s_carry = 0;
    __syncthreads();
    for (int base = 0; base < N; base += 1024) {
        int i = base + tid;
        int v = (i < N) ? g_counts[i] : 0;
        int incl = v;
        #pragma unroll
        for (int off = 1; off < 32; off <<= 1) {
            int t = __shfl_up_sync(0xffffffffu, incl, off);
            if (lane >= off) incl += t;
        }
        if (lane == 31) warp_off[wid] = incl;
        __syncthreads();
        if (wid == 0) {
            int s = warp_off[lane];
            int si = s;
            #pragma unroll
            for (int off = 1; off < 32; off <<= 1) {
                int t = __shfl_up_sync(0xffffffffu, si, off);
                if (lane >= off) si += t;
            }
            warp_off[lane] = si - s;
        }
        __syncthreads();
        int excl = incl - v + warp_off[wid] + s_carry;
        if (i < N) { g_rowptr[i] = excl; g_cursor[i] = excl; }
        __syncthreads();
        if (tid == 1023) s_carry = excl + v;
        __syncthreads();
    }
    if (tid == 0) g_rowptr[N] = s_carry;
}

__global__ void scatter_kernel(const int* __restrict__ ei,
                               const float* __restrict__ attr, int E) {
    int e = blockIdx.x * blockDim.x + threadIdx.x;
    if (e >= E) return;
    int src = ei[e];
    int dst = ei[E + e];

    float p0 = attr[2 * e + 0];
    float p1 = attr[2 * e + 1];
    float v0 = p0 * 4.0f, v1 = p1 * 4.0f;
    float l0 = floorf(v0), l1 = floorf(v1);
    float f0 = v0 - l0,    f1 = v1 - l1;
    int i0 = (int)l0, i1 = (int)l1;
    int i00 = min(max(i0, 0), 4);
    int i01 = min(max(i0 + 1, 0), 4);
    int i10 = min(max(i1, 0), 4);
    int i11 = min(max(i1 + 1, 0), 4);

    float4 b;
    b.x = (1.0f - f0) * (1.0f - f1);
    b.y = (1.0f - f0) * f1;
    b.z = f0 * (1.0f - f1);
    b.w = f0 * f1;
    int wp = (i00 + 5 * i10)
           | ((i00 + 5 * i11) << 8)
           | ((i01 + 5 * i10) << 16)
           | ((i01 + 5 * i11) << 24);

    int pos = atomicAdd(&g_cursor[dst], 1);
    g_meta[2 * pos]     = make_float4(__int_as_float(src), __int_as_float(wp),
                                      b.x, b.y);
    g_meta[2 * pos + 1] = make_float4(b.z, b.w, 0.f, 0.f);
}

// ---------------- HMMA GEMM, k-batched, double-buffered W, smem epilogue -----
#define KBATCH 5
__global__ void __launch_bounds__(128, 4)
gemm_xw_hmma(const __half* __restrict__ X16,
             const __half* __restrict__ W16, int N) {
    __shared__ __half xs[128][72];
    __shared__ __half ws[2][64][72];
    int row0 = blockIdx.x * 128;
    int k0   = blockIdx.y * KBATCH;
    int tid  = threadIdx.x;

    #pragma unroll
    for (int t = tid; t < 1024; t += 128) {
        int r = t >> 3, c8 = (t & 7) * 8;
        int gr = row0 + r;
        uint4 v = make_uint4(0, 0, 0, 0);
        if (gr < N) v = *(const uint4*)&X16[(size_t)gr * CDIM + c8];
        *(uint4*)&xs[r][c8] = v;
    }
    #pragma unroll
    for (int t = tid; t < 512; t += 128) {
        int r = t >> 3, c8 = (t & 7) * 8;
        *(uint4*)&ws[0][r][c8] = *(const uint4*)&W16[k0 * 4096 + r * 64 + c8];
    }
    __syncthreads();

    int warp = tid >> 5, lane = tid & 31;
    int m_base = warp * 32;

    uint32 a[2][4][4];
    #pragma unroll
    for (int mt = 0; mt < 2; ++mt)
        #pragma unroll
        for (int kt = 0; kt < 4; ++kt) {
            uint32 addr = (uint32)__cvta_generic_to_shared(
                &xs[m_base + mt * 16 + (lane & 15)][kt * 16 + (lane >> 4) * 8]);
            ldsm_x4(a[mt][kt], addr);
        }

    for (int kk = 0; kk < KBATCH; ++kk) {
        int k   = k0 + kk;
        int cur = kk & 1;

        if (kk + 1 < KBATCH) {
            #pragma unroll
            for (int t = tid; t < 512; t += 128) {
                int r = t >> 3, c8 = (t & 7) * 8;
                *(uint4*)&ws[cur ^ 1][r][c8] =
                    *(const uint4*)&W16[(k + 1) * 4096 + r * 64 + c8];
            }
        }

        float c[2][8][4];
        #pragma unroll
        for (int mt = 0; mt < 2; ++mt)
            #pragma unroll
            for (int nt = 0; nt < 8; ++nt)
                #pragma unroll
                for (int j = 0; j < 4; ++j) c[mt][nt][j] = 0.f;

        #pragma unroll
        for (int kt = 0; kt < 4; ++kt) {
            #pragma unroll
            for (int nt = 0; nt < 8; ++nt) {
                uint32 baddr = (uint32)__cvta_generic_to_shared(
                    &ws[cur][kt * 16 + (lane & 15)][nt * 8]);
                uint32 b0, b1;
                ldsm_x2t(b0, b1, baddr);
                mma16816(c[0][nt], a[0][kt], b0, b1);
                mma16816(c[1][nt], a[1][kt], b0, b1);
            }
        }

        int fr = lane >> 2;
        int fc = 2 * (lane & 3);
        #pragma unroll
        for (int mt = 0; mt < 2; ++mt) {
            #pragma unroll
            for (int nt = 0; nt < 8; ++nt) {
                *(__half2*)&xs[m_base + mt * 16 + fr][nt * 8 + fc] =
                    __floats2half2_rn(c[mt][nt][0], c[mt][nt][1]);
                *(__half2*)&xs[m_base + mt * 16 + 8 + fr][nt * 8 + fc] =
                    __floats2half2_rn(c[mt][nt][2], c[mt][nt][3]);
            }
        }
        __syncwarp();
        #pragma unroll
        for (int it = 0; it < 8; ++it) {
            int r  = m_base + it * 4 + (lane >> 3);
            int gr = row0 + r;
            if (gr < N) {
                uint4 v = *(uint4*)&xs[r][(lane & 7) * 8];
                *(uint4*)&g_xW[(size_t)gr * KO + k * 64 + (lane & 7) * 8] = v;
            }
        }
        __syncthreads();
    }
}

// ---------------- per-node aggregation: persistent, per-warp work stealing ---
__device__ __forceinline__ float2 edge_msg(int e, int lane) {
    float4 ma = g_meta[2 * e];
    float4 mb = g_meta[2 * e + 1];
    int src    = __float_as_int(ma.x);
    unsigned w = (unsigned)__float_as_int(ma.y);
    const __half2* p = (const __half2*)(g_xW + (size_t)src * KO) + lane;
    __half2 a0 = ldcg_h2(p + ((w      ) & 255) * 32);
    __half2 a1 = ldcg_h2(p + ((w >>  8) & 255) * 32);
    __half2 a2 = ldcg_h2(p + ((w >> 16) & 255) * 32);
    __half2 a3 = ldcg_h2(p + ((w >> 24) & 255) * 32);
    float2 f, v;
    f = __half22float2(a0); v.x = ma.z * f.x;           v.y = ma.z * f.y;
    f = __half22float2(a1); v.x = fmaf(ma.w, f.x, v.x); v.y = fmaf(ma.w, f.y, v.y);
    f = __half22float2(a2); v.x = fmaf(mb.x, f.x, v.x); v.y = fmaf(mb.x, f.y, v.y);
    f = __half22float2(a3); v.x = fmaf(mb.y, f.x, v.x); v.y = fmaf(mb.y, f.y, v.y);
    return v;
}

__global__ void __launch_bounds__(256, 3)
agg_kernel(const float* __restrict__ xin,
           const float* __restrict__ root,
           const float* __restrict__ bias,
           float* __restrict__ xout,
           __half* __restrict__ xout16, int N, int layer) {
    __shared__ float sx[8][64];
    int wib  = threadIdx.x >> 5;
    int lane = threadIdx.x & 31;
    int c0   = lane * 2;
    float2 bz = make_float2(bias[c0], bias[c0 + 1]);

    for (;;) {
        int n = 0;
        if (lane == 0) n = atomicAdd(&g_work[layer], 1);
        n = __shfl_sync(0xffffffffu, n, 0);
        if (n >= N) break;

        // stage this node's x row into the warp's smem slice
        __syncwarp();   // prior iteration's readers done before overwrite
        float2 xv = *(const float2*)&xin[(size_t)n * CDIM + c0];
        sx[wib][c0]     = xv.x;
        sx[wib][c0 + 1] = xv.y;
        __syncwarp();

        float2 r2 = bz;
        #pragma unroll
        for (int i = 0; i < CDIM; ++i) {
            float  xi = sx[wib][i];
            float2 rv = *(const float2*)&root[i * CDIM + c0];
            r2.x = fmaf(xi, rv.x, r2.x);
            r2.y = fmaf(xi, rv.y, r2.y);
        }

        int beg = g_rowptr[n];
        int end = g_rowptr[n + 1];
        const float NEG = __int_as_float(0xff800000);
        float2 m0 = make_float2(NEG, NEG);
        float2 m1 = make_float2(NEG, NEG);
        float2 m2 = make_float2(NEG, NEG);
        float2 m3 = make_float2(NEG, NEG);
        int e = beg;
        for (; e + 3 < end; e += 4) {
            float4 ma[4], mb[4];
            #pragma unroll
            for (int j = 0; j < 4; ++j) {
                ma[j] = g_meta[2 * (e + j)];
                mb[j] = g_meta[2 * (e + j) + 1];
            }
            __half2 h[4][4];
            #pragma unroll
            for (int j = 0; j < 4; ++j) {
                int src    = __float_as_int(ma[j].x);
                unsigned w = (unsigned)__float_as_int(ma[j].y);
                const __half2* p = (const __half2*)(g_xW + (size_t)src * KO) + lane;
                h[j][0] = ldcg_h2(p + ((w      ) & 255) * 32);
                h[j][1] = ldcg_h2(p + ((w >>  8) & 255) * 32);
                h[j][2] = ldcg_h2(p + ((w >> 16) & 255) * 32);
                h[j][3] = ldcg_h2(p + ((w >> 24) & 255) * 32);
            }
            #pragma unroll
            for (int j = 0; j < 4; ++j) {
                float2 f, v;
                f = __half22float2(h[j][0]); v.x = ma[j].z * f.x;           v.y = ma[j].z * f.y;
                f = __half22float2(h[j][1]); v.x = fmaf(ma[j].w, f.x, v.x); v.y = fmaf(ma[j].w, f.y, v.y);
                f = __half22float2(h[j][2]); v.x = fmaf(mb[j].x, f.x, v.x); v.y = fmaf(mb[j].x, f.y, v.y);
                f = __half22float2(h[j][3]); v.x = fmaf(mb[j].y, f.x, v.x); v.y = fmaf(mb[j].y, f.y, v.y);
                if (j == 0) { m0.x = fmaxf(m0.x, v.x); m0.y = fmaxf(m0.y, v.y); }
                if (j == 1) { m1.x = fmaxf(m1.x, v.x); m1.y = fmaxf(m1.y, v.y); }
                if (j == 2) { m2.x = fmaxf(m2.x, v.x); m2.y = fmaxf(m2.y, v.y); }
                if (j == 3) { m3.x = fmaxf(m3.x, v.x); m3.y = fmaxf(m3.y, v.y); }
            }
        }
        for (; e < end; ++e) {
            float2 v = edge_msg(e, lane);
            m0.x = fmaxf(m0.x, v.x); m0.y = fmaxf(m0.y, v.y);
        }
        float2 m = make_float2(fmaxf(fmaxf(m0.x, m1.x), fmaxf(m2.x, m3.x)),
                               fmaxf(fmaxf(m0.y, m1.y), fmaxf(m2.y, m3.y)));
        float2 agg = (end > beg) ? m : make_float2(0.f, 0.f);
        float2 o = make_float2(fmaxf(agg.x + r2.x, 0.f), fmaxf(agg.y + r2.y, 0.f));
        *(float2*)&xout[(size_t)n * CDIM + c0] = o;
        *(__half2*)&xout16[(size_t)n * CDIM + c0] = __floats2half2_rn(o.x, o.y);
    }
}

// ---------------- final gemm, split into partial (x, x1) and finish (x2) -----
__global__ void partial_final_kernel(const float* __restrict__ x,
                                     const float* __restrict__ fw, int N) {
    __shared__ float2 As2[64][64];
    __shared__ float  Bs[64][64];
    int row0 = blockIdx.x * 128;
    int tid  = threadIdx.x;
    int tx = tid & 7, ty = tid >> 3;

    float2 acc[4][8];
    #pragma unroll
    for (int rp = 0; rp < 4; ++rp)
        #pragma unroll
        for (int c = 0; c < 8; ++c) acc[rp][c] = make_float2(0.f, 0.f);

    for (int ch = 0; ch < 2; ++ch) {
        const float* S = (ch == 0) ? x : g_x1;
        __syncthreads();
        #pragma unroll
        for (int t = tid; t < 128 * 16; t += 128) {
            int r = t >> 4, c4 = (t & 15) * 4;
            int gr = row0 + r;
            float4 v = make_float4(0.f, 0.f, 0.f, 0.f);
            if (gr < N) v = *(const float4*)&S[(size_t)gr * CDIM + c4];
            float* dstp0 = (float*)&As2[r >> 1][c4 + 0];
            int l = r & 1;
            dstp0[l]     = v.x;
            dstp0[2 + l] = v.y;
            dstp0[4 + l] = v.z;
            dstp0[6 + l] = v.w;
        }
        #pragma unroll
        for (int t = tid; t < 64 * 16; t += 128) {
            int r = t >> 4, c4 = (t & 15) * 4;
            *(float4*)&Bs[r][c4] = *(const float4*)&fw[ch * 4096 + r * 64 + c4];
        }
        __syncthreads();

        #pragma unroll 16
        for (int i = 0; i < 64; ++i) {
            float2 ap[4];
            #pragma unroll
            for (int rp = 0; rp < 4; ++rp) ap[rp] = As2[ty * 4 + rp][i];
            float4 b0 = *(const float4*)&Bs[i][tx * 8];
            float4 b1 = *(const float4*)&Bs[i][tx * 8 + 4];
            ull bb[8];
            bb[0] = dup2(b0.x); bb[1] = dup2(b0.y); bb[2] = dup2(b0.z); bb[3] = dup2(b0.w);
            bb[4] = dup2(b1.x); bb[5] = dup2(b1.y); bb[6] = dup2(b1.z); bb[7] = dup2(b1.w);
            #pragma unroll
            for (int rp = 0; rp < 4; ++rp)
                #pragma unroll
                for (int c = 0; c < 8; ++c)
                    acc[rp][c] = ffma2(ap[rp], bb[c], acc[rp][c]);
        }
    }

    #pragma unroll
    for (int rp = 0; rp < 4; ++rp) {
        int r0 = row0 + ty * 8 + rp * 2;
        if (r0 < N) {
            float4 v0 = make_float4(acc[rp][0].x, acc[rp][1].x, acc[rp][2].x, acc[rp][3].x);
            float4 v1 = make_float4(acc[rp][4].x, acc[rp][5].x, acc[rp][6].x, acc[rp][7].x);
            *(float4*)&g_facc[(size_t)r0 * CDIM + tx * 8]     = v0;
            *(float4*)&g_facc[(size_t)r0 * CDIM + tx * 8 + 4] = v1;
        }
        if (r0 + 1 < N) {
            float4 v0 = make_float4(acc[rp][0].y, acc[rp][1].y, acc[rp][2].y, acc[rp][3].y);
            float4 v1 = make_float4(acc[rp][4].y, acc[rp][5].y, acc[rp][6].y, acc[rp][7].y);
            *(float4*)&g_facc[(size_t)(r0 + 1) * CDIM + tx * 8]     = v0;
            *(float4*)&g_facc[(size_t)(r0 + 1) * CDIM + tx * 8 + 4] = v1;
        }
    }
}

__global__ void finish_final_kernel(const float* __restrict__ fw,
                                    const float* __restrict__ fb,
                                    float* __restrict__ out, int N) {
    __shared__ float2 As2[64][64];
    __shared__ float  Bs[64][64];
    int row0 = blockIdx.x * 128;
    int tid  = threadIdx.x;
    int tx = tid & 7, ty = tid >> 3;

    float2 acc[4][8];
    #pragma unroll
    for (int rp = 0; rp < 4; ++rp)
        #pragma unroll
        for (int c = 0; c < 8; ++c) acc[rp][c] = make_float2(0.f, 0.f);

    #pragma unroll
    for (int t = tid; t < 128 * 16; t += 128) {
        int r = t >> 4, c4 = (t & 15) * 4;
        int gr = row0 + r;
        float4 v = make_float4(0.f, 0.f, 0.f, 0.f);
        if (gr < N) v = *(const float4*)&g_x2[(size_t)gr * CDIM + c4];
        float* dstp0 = (float*)&As2[r >> 1][c4 + 0];
        int l = r & 1;
        dstp0[l]     = v.x;
        dstp0[2 + l] = v.y;
        dstp0[4 + l] = v.z;
        dstp0[6 + l] = v.w;
    }
    #pragma unroll
    for (int t = tid; t < 64 * 16; t += 128) {
        int r = t >> 4, c4 = (t & 15) * 4;
        *(float4*)&Bs[r][c4] = *(const float4*)&fw[2 * 4096 + r * 64 + c4];
    }
    __syncthreads();

    #pragma unroll 16
    for (int i = 0; i < 64; ++i) {
        float2 ap[4];
        #pragma unroll
        for (int rp = 0; rp < 4; ++rp) ap[rp] = As2[ty * 4 + rp][i];
        float4 b0 = *(const float4*)&Bs[i][tx * 8];
        float4 b1 = *(const float4*)&Bs[i][tx * 8 + 4];
        ull bb[8];
        bb[0] = dup2(b0.x); bb[1] = dup2(b0.y); bb[2] = dup2(b0.z); bb[3] = dup2(b0.w);
        bb[4] = dup2(b1.x); bb[5] = dup2(b1.y); bb[6] = dup2(b1.z); bb[7] = dup2(b1.w);
        #pragma unroll
        for (int rp = 0; rp < 4; ++rp)
            #pragma unroll
            for (int c = 0; c < 8; ++c)
                acc[rp][c] = ffma2(ap[rp], bb[c], acc[rp][c]);
    }

    float4 fb0 = *(const float4*)&fb[tx * 8];
    float4 fb1 = *(const float4*)&fb[tx * 8 + 4];
    #pragma unroll
    for (int rp = 0; rp < 4; ++rp) {
        int r0 = row0 + ty * 8 + rp * 2;
        if (r0 < N) {
            float4 p0 = *(const float4*)&g_facc[(size_t)r0 * CDIM + tx * 8];
            float4 p1 = *(const float4*)&g_facc[(size_t)r0 * CDIM + tx * 8 + 4];
            float4 v0 = make_float4(acc[rp][0].x + p0.x + fb0.x, acc[rp][1].x + p0.y + fb0.y,
                                    acc[rp][2].x + p0.z + fb0.z, acc[rp][3].x + p0.w + fb0.w);
            float4 v1 = make_float4(acc[rp][4].x + p1.x + fb1.x, acc[rp][5].x + p1.y + fb1.y,
                                    acc[rp][6].x + p1.z + fb1.z, acc[rp][7].x + p1.w + fb1.w);
            *(float4*)&out[(size_t)r0 * CDIM + tx * 8]     = v0;
            *(float4*)&out[(size_t)r0 * CDIM + tx * 8 + 4] = v1;
        }
        if (r0 + 1 < N) {
            float4 p0 = *(const float4*)&g_facc[(size_t)(r0 + 1) * CDIM + tx * 8];
            float4 p1 = *(const float4*)&g_facc[(size_t)(r0 + 1) * CDIM + tx * 8 + 4];
            float4 v0 = make_float4(acc[rp][0].y + p0.x + fb0.x, acc[rp][1].y + p0.y + fb0.y,
                                    acc[rp][2].y + p0.z + fb0.z, acc[rp][3].y + p0.w + fb0.w);
            float4 v1 = make_float4(acc[rp][4].y + p1.x + fb1.x, acc[rp][5].y + p1.y + fb1.y,
                                    acc[rp][6].y + p1.z + fb1.z, acc[rp][7].y + p1.w + fb1.w);
            *(float4*)&out[(size_t)(r0 + 1) * CDIM + tx * 8]     = v0;
            *(float4*)&out[(size_t)(r0 + 1) * CDIM + tx * 8 + 4] = v1;
        }
    }
}

// ---------------- launch -----------------------------------------------------
extern "C" void kernel_launch(void* const* d_in, const int* in_sizes, int n_in,
                              void* d_out, int out_size) {
    const float* x     = (const float*)d_in[0];
    const int*   ei    = (const int*)  d_in[1];
    const float* attr  = (const float*)d_in[2];
    const float* W1    = (const float*)d_in[3];
    const float* root1 = (const float*)d_in[4];
    const float* b1    = (const float*)d_in[5];
    const float* W2    = (const float*)d_in[6];
    const float* root2 = (const float*)d_in[7];
    const float* b2    = (const float*)d_in[8];
    const float* fw    = (const float*)d_in[9];
    const float* fb    = (const float*)d_in[10];
    float* out = (float*)d_out;

    int N = in_sizes[0] / CDIM;
    int E = in_sizes[1] / 2;
    if (N > MAXN) N = MAXN;
    if (E > MAXE) E = MAXE;

    float *px1 = nullptr, *px2 = nullptr;
    __half *px16 = nullptr, *pw16a = nullptr, *pw16b = nullptr;
    cudaGetSymbolAddress((void**)&px1, g_x1);
    cudaGetSymbolAddress((void**)&px2, g_x2);
    cudaGetSymbolAddress((void**)&px16, g_x16);
    cudaGetSymbolAddress((void**)&pw16a, g_W16a);
    cudaGetSymbolAddress((void**)&pw16b, g_W16b);

    int eb = (E + 255) / 256;
    int nb = (N + 255) / 256;
    dim3 ggrid((N + 127) / 128, KK / KBATCH);
    int ab = 456;   // persistent: 152 SMs x 3 blocks
    int fgrid = (N + 127) / 128;

    int xq = N * CDIM / 4;
    int wq = KK * CDIM * CDIM / 4;

    cudaStream_t s1 = g_ss.s1;
    cudaStream_t s2 = g_ss.s2;

    // fork from harness stream
    cudaEventRecord(g_ss.ev_fork, 0);
    cudaStreamWaitEvent(s1, g_ss.ev_fork, 0);
    cudaStreamWaitEvent(s2, g_ss.ev_fork, 0);

    // side stream: CSR build + W2 conversion
    zero_counts_kernel<<<nb, 256, 0, s2>>>(N);
    count_kernel<<<eb, 256, 0, s2>>>(ei, E);
    scan_kernel<<<1, 1024, 0, s2>>>(N);
    scatter_kernel<<<eb, 256, 0, s2>>>(ei, attr, E);
    f2h_kernel<<<(wq + 255) / 256, 256, 0, s2>>>(W2, pw16b, wq);
    cudaEventRecord(g_ss.ev_csr, s2);

    // main chain on s1
    f2h_kernel<<<(xq + 255) / 256, 256, 0, s1>>>(x, px16, xq);
    f2h_kernel<<<(wq + 255) / 256, 256, 0, s1>>>(W1, pw16a, wq);
    gemm_xw_hmma<<<ggrid, 128, 0, s1>>>(px16, pw16a, N);
    cudaStreamWaitEvent(s1, g_ss.ev_csr, 0);
    agg_kernel<<<ab, 256, 0, s1>>>(x, root1, b1, px1, px16, N, 0);
    cudaEventRecord(g_ss.ev_agg1, s1);

    // side stream: partial final (x, x1) overlaps layer 2
    cudaStreamWaitEvent(s2, g_ss.ev_agg1, 0);
    partial_final_kernel<<<fgrid, 128, 0, s2>>>(x, fw, N);
    cudaEventRecord(g_ss.ev_pf, s2);

    // layer 2 on s1
    gemm_xw_hmma<<<ggrid, 128, 0, s1>>>(px16, pw16b, N);
    agg_kernel<<<ab, 256, 0, s1>>>(px1, root2, b2, px2, px16, N, 1);

    // finish final on s1
    cudaStreamWaitEvent(s1, g_ss.ev_pf, 0);
    finish_final_kernel<<<fgrid, 128, 0, s1>>>(fw, fb, out, N);

    // join back to harness stream
    cudaEventRecord(g_ss.ev_done, s1);
    cudaStreamWaitEvent(0, g_ss.ev_done, 0);
}